// round 7
// baseline (speedup 1.0000x reference)
#include <cuda_runtime.h>
#include <cstdint>

#define MARGIN   500.0f
#define NBLOCKS  128
#define NTHREADS 256   // 128 * 256 = 32768 threads, 1 element each

__device__ float        g_accum = 0.0f;  // read-and-zeroed by winner's exch
__device__ unsigned int g_count = 0;     // reset to 0 by winner's exch

__global__ __launch_bounds__(NTHREADS)
void contrastive_last_anchor_fused(const int* __restrict__ labels,
                                   const float* __restrict__ coords,
                                   float* __restrict__ out,
                                   int n)
{
    const int i = blockIdx.x * NTHREADS + threadIdx.x;

    // Anchor = last row (broadcast loads -> L1 hit for all but first requester)
    const int   anchor_lab = labels[n - 1];
    const float ax = coords[3 * n - 3];
    const float ay = coords[3 * n - 2];
    const float az = coords[3 * n - 1];

    float v = 0.0f;
    if (i < n) {
        const float dx = ax - coords[3 * i + 0];
        const float dy = ay - coords[3 * i + 1];
        const float dz = az - coords[3 * i + 2];
        const float d  = dx * dx + dy * dy + dz * dz;
        v = (labels[i] == anchor_lab) ? d : fmaxf(0.0f, MARGIN - d);
    }

    // Warp reduction
    #pragma unroll
    for (int off = 16; off > 0; off >>= 1)
        v += __shfl_down_sync(0xFFFFFFFFu, v, off);

    __shared__ float s_warp[NTHREADS / 32];  // 8 warps
    if ((threadIdx.x & 31) == 0)
        s_warp[threadIdx.x >> 5] = v;
    __syncthreads();

    // Tail: all atomics are NATIVE ATOMG/REDG ops (ADD / EXCH). Do NOT use
    // atom.inc here — ATOMG has no INC on sm_103a, ptxas lowers it to a CAS
    // retry loop that serializes ~318cyc/retry under 128-way contention.
    if (threadIdx.x == 0) {
        float part = 0.0f;
        #pragma unroll
        for (int w = 0; w < NTHREADS / 32; w++)
            part += s_warp[w];

        // Native REDG.ADD.F32 with release: partial visible to counter-acquirer.
        asm volatile("red.release.gpu.global.add.f32 [%0], %1;"
                     :: "l"(&g_accum), "f"(part) : "memory");

        // Native ATOMG.ADD election (acq_rel: joins the release sequence).
        unsigned int old;
        asm volatile("atom.acq_rel.gpu.global.add.u32 %0, [%1], %2;"
                     : "=r"(old) : "l"(&g_count), "r"(1u) : "memory");

        if (old == NBLOCKS - 1) {
            // Read grid total AND reset accumulator to 0.0f (native EXCH).
            unsigned int total_bits;
            asm volatile("atom.acquire.gpu.global.exch.b32 %0, [%1], %2;"
                         : "=r"(total_bits) : "l"(&g_accum), "r"(0u)
                         : "memory");
            out[0] = __uint_as_float(total_bits);

            // Reset the election counter for the next graph replay.
            unsigned int dummy;
            asm volatile("atom.relaxed.gpu.global.exch.b32 %0, [%1], %2;"
                         : "=r"(dummy) : "l"(&g_count), "r"(0u)
                         : "memory");
        }
    }
}

extern "C" void kernel_launch(void* const* d_in, const int* in_sizes, int n_in,
                              void* d_out, int out_size)
{
    const int*   labels = (const int*)d_in[0];
    const float* coords = (const float*)d_in[1];
    float*       out    = (float*)d_out;
    const int n = in_sizes[0];  // 32768

    contrastive_last_anchor_fused<<<NBLOCKS, NTHREADS>>>(labels, coords, out, n);
}

// round 9
// speedup vs baseline: 1.2963x; 1.2963x over previous
#include <cuda_runtime.h>
#include <cstdint>

#define MARGIN   500.0f
#define NBLOCKS  128
#define NTHREADS 256   // 128 * 256 = 32768 threads, 1 element each

__device__ float g_partials[NBLOCKS];   // overwritten every run (plain STG)

__global__ __launch_bounds__(NTHREADS)
void loss_partials_kernel(const int* __restrict__ labels,
                          const float* __restrict__ coords,
                          int n)
{
    const int i = blockIdx.x * NTHREADS + threadIdx.x;

    // Anchor = last row (broadcast loads -> L1 hit for all but first requester)
    const int   anchor_lab = labels[n - 1];
    const float ax = coords[3 * n - 3];
    const float ay = coords[3 * n - 2];
    const float az = coords[3 * n - 1];

    float v = 0.0f;
    if (i < n) {
        const float dx = ax - coords[3 * i + 0];
        const float dy = ay - coords[3 * i + 1];
        const float dz = az - coords[3 * i + 2];
        const float d  = dx * dx + dy * dy + dz * dz;
        v = (labels[i] == anchor_lab) ? d : fmaxf(0.0f, MARGIN - d);
    }

    // Warp reduction
    #pragma unroll
    for (int off = 16; off > 0; off >>= 1)
        v += __shfl_down_sync(0xFFFFFFFFu, v, off);

    __shared__ float s_warp[NTHREADS / 32];  // 8 warps
    if ((threadIdx.x & 31) == 0)
        s_warp[threadIdx.x >> 5] = v;
    __syncthreads();

    // Plain store of the block partial. No atomics, no fences, no election:
    // visibility to the dependent grid is provided by the PDL completion
    // trigger (implicit at kernel exit -> full memory flush).
    if (threadIdx.x == 0) {
        float part = 0.0f;
        #pragma unroll
        for (int w = 0; w < NTHREADS / 32; w++)
            part += s_warp[w];
        g_partials[blockIdx.x] = part;
    }
}

__global__ __launch_bounds__(32)
void final_reduce_kernel(float* __restrict__ out)
{
    // Launched with programmatic stream serialization: we are already resident
    // while loss_partials_kernel runs; this blocks until it completes+flushes.
    cudaGridDependencySynchronize();

    const float4 p = ((const float4*)g_partials)[threadIdx.x];  // 32 x 4 = 128
    float v = (p.x + p.y) + (p.z + p.w);

    #pragma unroll
    for (int off = 16; off > 0; off >>= 1)
        v += __shfl_down_sync(0xFFFFFFFFu, v, off);

    if (threadIdx.x == 0)
        out[0] = v;
}

extern "C" void kernel_launch(void* const* d_in, const int* in_sizes, int n_in,
                              void* d_out, int out_size)
{
    const int*   labels = (const int*)d_in[0];
    const float* coords = (const float*)d_in[1];
    float*       out    = (float*)d_out;
    const int n = in_sizes[0];  // 32768

    loss_partials_kernel<<<NBLOCKS, NTHREADS>>>(labels, coords, n);

    // Second kernel with programmatic dependent launch: its launch latency
    // overlaps kernel1's execution; it blocks inside on griddep-sync.
    cudaLaunchAttribute attr[1];
    attr[0].id = cudaLaunchAttributeProgrammaticStreamSerialization;
    attr[0].val.programmaticStreamSerializationAllowed = 1;

    cudaLaunchConfig_t cfg = {};
    cfg.gridDim  = dim3(1, 1, 1);
    cfg.blockDim = dim3(32, 1, 1);
    cfg.dynamicSmemBytes = 0;
    cfg.stream   = 0;
    cfg.attrs    = attr;
    cfg.numAttrs = 1;

    cudaLaunchKernelEx(&cfg, final_reduce_kernel, out);
}

// round 10
// speedup vs baseline: 1.3462x; 1.0385x over previous
#include <cuda_runtime.h>
#include <cstdint>

#define MARGIN   500.0f
#define NBLOCKS  128
#define NTHREADS 256   // 128 * 256 = 32768 threads, 1 element each

__device__ float g_accum = 0.0f;   // REDG target; read-and-zeroed by kernel2

__global__ __launch_bounds__(NTHREADS)
void loss_partials_kernel(const int* __restrict__ labels,
                          const float* __restrict__ coords,
                          int n)
{
    const int i = blockIdx.x * NTHREADS + threadIdx.x;

    // Anchor = last row (broadcast loads -> L1 hit for all but first requester)
    const int   anchor_lab = labels[n - 1];
    const float ax = coords[3 * n - 3];
    const float ay = coords[3 * n - 2];
    const float az = coords[3 * n - 1];

    float v = 0.0f;
    if (i < n) {
        const float dx = ax - coords[3 * i + 0];
        const float dy = ay - coords[3 * i + 1];
        const float dz = az - coords[3 * i + 2];
        const float d  = dx * dx + dy * dy + dz * dz;
        v = (labels[i] == anchor_lab) ? d : fmaxf(0.0f, MARGIN - d);
    }

    // Warp reduction
    #pragma unroll
    for (int off = 16; off > 0; off >>= 1)
        v += __shfl_down_sync(0xFFFFFFFFu, v, off);

    __shared__ float s_warp[NTHREADS / 32];  // 8 warps
    if ((threadIdx.x & 31) == 0)
        s_warp[threadIdx.x >> 5] = v;
    __syncthreads();

    if (threadIdx.x == 0) {
        float part = 0.0f;
        #pragma unroll
        for (int w = 0; w < NTHREADS / 32; w++)
            part += s_warp[w];
        // Fire-and-forget REDG.ADD.F32 into one L2 word (R1's proven tail).
        asm volatile("red.global.add.f32 [%0], %1;"
                     :: "l"(&g_accum), "f"(part) : "memory");
    }

    // Release the dependent grid NOW (all blocks must trigger) — before this
    // kernel's drain/teardown. Writes issued before the trigger are visible
    // to the dependent grid after its griddep-wait.
    cudaTriggerProgrammaticLaunchCompletion();
}

__global__ __launch_bounds__(32)
void final_store_kernel(float* __restrict__ out)
{
    // Resident while kernel1 runs; wait releases once all 128 blocks trigger.
    cudaGridDependencySynchronize();

    if (threadIdx.x == 0) {
        // Atomically read the grid total AND reset the accumulator to 0.0f
        // (deterministic across graph replays).
        unsigned int bits;
        asm volatile("atom.acquire.gpu.global.exch.b32 %0, [%1], %2;"
                     : "=r"(bits) : "l"(&g_accum), "r"(0u) : "memory");
        out[0] = __uint_as_float(bits);
    }
}

extern "C" void kernel_launch(void* const* d_in, const int* in_sizes, int n_in,
                              void* d_out, int out_size)
{
    const int*   labels = (const int*)d_in[0];
    const float* coords = (const float*)d_in[1];
    float*       out    = (float*)d_out;
    const int n = in_sizes[0];  // 32768

    loss_partials_kernel<<<NBLOCKS, NTHREADS>>>(labels, coords, n);

    cudaLaunchAttribute attr[1];
    attr[0].id = cudaLaunchAttributeProgrammaticStreamSerialization;
    attr[0].val.programmaticStreamSerializationAllowed = 1;

    cudaLaunchConfig_t cfg = {};
    cfg.gridDim  = dim3(1, 1, 1);
    cfg.blockDim = dim3(32, 1, 1);
    cfg.dynamicSmemBytes = 0;
    cfg.stream   = 0;
    cfg.attrs    = attr;
    cfg.numAttrs = 1;

    cudaLaunchKernelEx(&cfg, final_store_kernel, out);
}